// round 1
// baseline (speedup 1.0000x reference)
#include <cuda_runtime.h>
#include <math.h>

// Problem constants
#define BB_   8
#define LL_   512
#define HEADS_ 12
#define HS_   64
#define HID_  768
#define OD_   1536          // HEADS*2*HS
#define M1_   (BB_*LL_)     // 4096 rows of GEMM1
#define BH_   (BB_*HEADS_)  // 96
#define NEG_INF_F (-3.4028234663852886e38f)  // finfo(float32).min == -FLT_MAX

// Scratch (device globals — no allocations allowed)
__device__ float g_q[BH_ * LL_ * HS_];   // [b*h][l][d]  12.58 MB
__device__ float g_k[BH_ * LL_ * HS_];   // [b*h][l][d]  12.58 MB
__device__ float g_sin[LL_ * (HS_/2)];   // [l][p] p=0..31
__device__ float g_cos[LL_ * (HS_/2)];

// ---------------------------------------------------------------------------
// Kernel 0: RoPE sin/cos tables, matching the fp32 reference recipe:
//   inv_freq[p] = 10000^(-p/32); angle = l * inv_freq[p]
// ---------------------------------------------------------------------------
__global__ void rope_table_kernel() {
    int idx = blockIdx.x * blockDim.x + threadIdx.x;
    if (idx >= LL_ * 32) return;
    int l = idx >> 5;
    int p = idx & 31;
    float inv = powf(10000.0f, -(float)p / 32.0f);
    float ang = (float)l * inv;
    g_sin[idx] = sinf(ang);
    g_cos[idx] = cosf(ang);
}

// ---------------------------------------------------------------------------
// Kernel 1: X = inputs @ W + b   (4096 x 1536, K=768), fused RoPE epilogue,
// scatter q/k to [b*h][l][d] scratch.
// Tiling: 128x128 block tile, K-tile 8, 256 threads, 8x8 per thread.
// ---------------------------------------------------------------------------
__global__ __launch_bounds__(256, 2)
void gemm1_rope_kernel(const float* __restrict__ A,     // [4096][768]
                       const float* __restrict__ W,     // [768][1536]
                       const float* __restrict__ bias)  // [1536]
{
    __shared__ float As[8][128];   // transposed: As[k][m]
    __shared__ float Bs[8][128];   // Bs[k][n]

    const int t  = threadIdx.x;
    const int tx = t & 15;         // 0..15 -> 8 cols each
    const int ty = t >> 4;         // 0..15 -> 8 rows each
    const int m0 = blockIdx.y * 128;
    const int n0 = blockIdx.x * 128;

    // global load assignments
    const int ar = t >> 1;          // 0..127 row within A tile
    const int ac = (t & 1) * 4;     // 0 or 4 (col within 8-wide K tile)
    const int br = t >> 5;          // 0..7 row within W K-tile
    const int bc = (t & 31) * 4;    // 0..124 col within 128-wide N tile

    const float* Ap = A + (size_t)(m0 + ar) * HID_ + ac;
    const float* Wp = W + (size_t)br * OD_ + n0 + bc;

    float acc[8][8];
    #pragma unroll
    for (int i = 0; i < 8; i++)
        #pragma unroll
        for (int j = 0; j < 8; j++) acc[i][j] = 0.0f;

    for (int k0 = 0; k0 < HID_; k0 += 8) {
        float4 a4 = *(const float4*)(Ap + k0);
        float4 b4 = *(const float4*)(Wp + (size_t)k0 * OD_);
        __syncthreads();   // previous tile fully consumed
        As[ac + 0][ar] = a4.x;
        As[ac + 1][ar] = a4.y;
        As[ac + 2][ar] = a4.z;
        As[ac + 3][ar] = a4.w;
        *(float4*)&Bs[br][bc] = b4;
        __syncthreads();

        #pragma unroll
        for (int kk = 0; kk < 8; kk++) {
            float4 a0 = *(const float4*)&As[kk][ty * 8];
            float4 a1 = *(const float4*)&As[kk][ty * 8 + 4];
            float4 b0 = *(const float4*)&Bs[kk][tx * 8];
            float4 b1 = *(const float4*)&Bs[kk][tx * 8 + 4];
            float ra[8] = {a0.x, a0.y, a0.z, a0.w, a1.x, a1.y, a1.z, a1.w};
            float rb[8] = {b0.x, b0.y, b0.z, b0.w, b1.x, b1.y, b1.z, b1.w};
            #pragma unroll
            for (int i = 0; i < 8; i++)
                #pragma unroll
                for (int j = 0; j < 8; j++)
                    acc[i][j] = fmaf(ra[i], rb[j], acc[i][j]);
        }
    }

    // Epilogue: bias + RoPE + scatter. Thread owns rows m0+ty*8+i,
    // cols n0+tx*8+j (8 contiguous cols => 4 complete even/odd RoPE pairs).
    const int ngbase = n0 + tx * 8;
    #pragma unroll
    for (int i = 0; i < 8; i++) {
        const int m  = m0 + ty * 8 + i;
        const int l  = m & (LL_ - 1);
        const int b_ = m >> 9;
        #pragma unroll
        for (int j = 0; j < 8; j += 2) {
            const int n = ngbase + j;        // even
            float e = acc[i][j]     + bias[n];
            float o = acc[i][j + 1] + bias[n + 1];
            const int h  = n >> 7;           // /128
            const int qk = (n >> 6) & 1;     // 0 = q, 1 = k
            const int d  = n & 63;
            const int p  = d >> 1;
            const float s = g_sin[l * 32 + p];
            const float c = g_cos[l * 32 + p];
            const float re = e * c - o * s;
            const float ro = e * s + o * c;
            float* dst = (qk ? g_k : g_q)
                       + ((size_t)(b_ * HEADS_ + h) * LL_ + l) * HS_ + d;
            dst[0] = re;
            dst[1] = ro;
        }
    }
}

// ---------------------------------------------------------------------------
// Kernel 2: logits[b,h,m,n] = (q[bh,m,:] . k[bh,n,:]) / 8, masked.
// neg_inf where (m > n) OR !am[b,m] OR !am[b,n].
// 64x64 output tile per block; tiles with tm > tn are fully masked -> fast fill.
// ---------------------------------------------------------------------------
__global__ __launch_bounds__(256, 2)
void attn_logits_kernel(const int* __restrict__ am,  // [8][512]
                        float* __restrict__ out)     // [96][512][512]
{
    const int bh = blockIdx.z;
    const int tm = blockIdx.y;
    const int tn = blockIdx.x;
    const int t  = threadIdx.x;
    const int b_ = bh / HEADS_;
    const int m0 = tm * 64;
    const int n0 = tn * 64;
    float* obase = out + (size_t)bh * LL_ * LL_;

    if (tm > tn) {
        // entire tile strictly below diagonal -> neg_inf, no compute/loads
        const float4 nv = make_float4(NEG_INF_F, NEG_INF_F, NEG_INF_F, NEG_INF_F);
        #pragma unroll
        for (int i = t; i < 1024; i += 256) {          // 64*64/4 float4s
            int r = i >> 4;
            int c = (i & 15) * 4;
            *(float4*)&obase[(size_t)(m0 + r) * LL_ + n0 + c] = nv;
        }
        return;
    }

    __shared__ float Qs[64][68];   // Qs[m][d]   (+4 pad: conflict-free, 16B-aligned rows)
    __shared__ float Kst[64][68];  // Kst[d][n]  transposed
    __shared__ int   rmv[64], cmv[64];

    const float* qb = g_q + ((size_t)bh * LL_ + m0) * HS_;
    const float* kb = g_k + ((size_t)bh * LL_ + n0) * HS_;

    #pragma unroll
    for (int i = t; i < 1024; i += 256) {
        int r = i >> 4;
        int c = (i & 15) * 4;
        *(float4*)&Qs[r][c] = *(const float4*)(qb + r * HS_ + c);
        float4 v = *(const float4*)(kb + r * HS_ + c);
        Kst[c + 0][r] = v.x;
        Kst[c + 1][r] = v.y;
        Kst[c + 2][r] = v.z;
        Kst[c + 3][r] = v.w;
    }
    if (t < 64)           rmv[t]      = am[b_ * LL_ + m0 + t];
    else if (t < 128)     cmv[t - 64] = am[b_ * LL_ + n0 + (t - 64)];
    __syncthreads();

    const int ty = t >> 4, tx = t & 15;
    const int mi = ty * 4, ni = tx * 4;

    float acc[4][4];
    #pragma unroll
    for (int i = 0; i < 4; i++)
        #pragma unroll
        for (int j = 0; j < 4; j++) acc[i][j] = 0.0f;

    #pragma unroll 8
    for (int kd = 0; kd < 64; kd++) {
        float4 kv = *(const float4*)&Kst[kd][ni];
        float q0 = Qs[mi + 0][kd];
        float q1 = Qs[mi + 1][kd];
        float q2 = Qs[mi + 2][kd];
        float q3 = Qs[mi + 3][kd];
        acc[0][0] = fmaf(q0, kv.x, acc[0][0]); acc[0][1] = fmaf(q0, kv.y, acc[0][1]);
        acc[0][2] = fmaf(q0, kv.z, acc[0][2]); acc[0][3] = fmaf(q0, kv.w, acc[0][3]);
        acc[1][0] = fmaf(q1, kv.x, acc[1][0]); acc[1][1] = fmaf(q1, kv.y, acc[1][1]);
        acc[1][2] = fmaf(q1, kv.z, acc[1][2]); acc[1][3] = fmaf(q1, kv.w, acc[1][3]);
        acc[2][0] = fmaf(q2, kv.x, acc[2][0]); acc[2][1] = fmaf(q2, kv.y, acc[2][1]);
        acc[2][2] = fmaf(q2, kv.z, acc[2][2]); acc[2][3] = fmaf(q2, kv.w, acc[2][3]);
        acc[3][0] = fmaf(q3, kv.x, acc[3][0]); acc[3][1] = fmaf(q3, kv.y, acc[3][1]);
        acc[3][2] = fmaf(q3, kv.z, acc[3][2]); acc[3][3] = fmaf(q3, kv.w, acc[3][3]);
    }

    #pragma unroll
    for (int i = 0; i < 4; i++) {
        const int m = m0 + mi + i;
        const bool rok = (rmv[mi + i] != 0);
        float4 res;
        float v[4];
        #pragma unroll
        for (int j = 0; j < 4; j++) {
            const int n = n0 + ni + j;
            float x = acc[i][j] * 0.125f;            // 1/sqrt(64)
            if (m > n || !rok || cmv[ni + j] == 0) x = NEG_INF_F;
            v[j] = x;
        }
        res.x = v[0]; res.y = v[1]; res.z = v[2]; res.w = v[3];
        *(float4*)&obase[(size_t)m * LL_ + n0 + ni] = res;
    }
}

// ---------------------------------------------------------------------------
// Entry point
// ---------------------------------------------------------------------------
extern "C" void kernel_launch(void* const* d_in, const int* in_sizes, int n_in,
                              void* d_out, int out_size) {
    const float* inputs = (const float*)d_in[0];  // [8,512,768]
    const float* W      = (const float*)d_in[1];  // [768,1536]
    const float* bias   = (const float*)d_in[2];  // [1536]
    const int*   amask  = (const int*)d_in[3];    // [8,512]
    float* out = (float*)d_out;                   // [8,12,512,512]

    rope_table_kernel<<<(LL_ * 32 + 255) / 256, 256>>>();
    gemm1_rope_kernel<<<dim3(OD_ / 128, M1_ / 128), 256>>>(inputs, W, bias);
    attn_logits_kernel<<<dim3(LL_ / 64, LL_ / 64, BH_), 256>>>(amask, out);
}

// round 2
// speedup vs baseline: 3.4471x; 3.4471x over previous
#include <cuda_runtime.h>
#include <math.h>
#include <stdint.h>

// Problem constants
#define BB_    8
#define LL_    512
#define HEADS_ 12
#define HS_    64
#define HID_   768
#define OD_    1536          // HEADS*2*HS
#define M1_    (BB_*LL_)     // 4096
#define BH_    (BB_*HEADS_)  // 96
#define NEG_INF_F (-3.4028234663852886e38f)

// Scratch (device globals — no allocations allowed)
__device__ float g_q[BH_ * LL_ * HS_];   // [b*h][l][d]
__device__ float g_k[BH_ * LL_ * HS_];   // [b*h][l][d]
__device__ float g_sin[LL_ * 32];
__device__ float g_cos[LL_ * 32];

// ---------------------------------------------------------------------------
// PTX helpers
// ---------------------------------------------------------------------------
__device__ __forceinline__ void cp_async16(void* smem, const void* gmem) {
    uint32_t s = (uint32_t)__cvta_generic_to_shared(smem);
    asm volatile("cp.async.ca.shared.global [%0], [%1], 16;\n" :: "r"(s), "l"(gmem));
}
#define CP_COMMIT() asm volatile("cp.async.commit_group;\n")
#define CP_WAIT0()  asm volatile("cp.async.wait_group 0;\n")

__device__ __forceinline__ uint32_t f2tf32(float x) {
    uint32_t r;
    asm("cvt.rna.tf32.f32 %0, %1;\n" : "=r"(r) : "f"(x));
    return r;
}

// D += A(m16k8,row) * B(k8n8,col), tf32 inputs, f32 accum
__device__ __forceinline__ void mma_tf32(float* d, const uint32_t* a, const uint32_t* b) {
    asm volatile(
        "mma.sync.aligned.m16n8k8.row.col.f32.tf32.tf32.f32 "
        "{%0,%1,%2,%3},{%4,%5,%6,%7},{%8,%9},{%0,%1,%2,%3};\n"
        : "+f"(d[0]), "+f"(d[1]), "+f"(d[2]), "+f"(d[3])
        : "r"(a[0]), "r"(a[1]), "r"(a[2]), "r"(a[3]), "r"(b[0]), "r"(b[1]));
}

// ---------------------------------------------------------------------------
// Kernel 0: RoPE sin/cos tables (fp32 recipe identical to reference)
// ---------------------------------------------------------------------------
__global__ void rope_table_kernel() {
    int idx = blockIdx.x * blockDim.x + threadIdx.x;
    if (idx >= LL_ * 32) return;
    int l = idx >> 5;
    int p = idx & 31;
    float inv = powf(10000.0f, -(float)p / 32.0f);
    float ang = (float)l * inv;
    g_sin[idx] = sinf(ang);
    g_cos[idx] = cosf(ang);
}

// ---------------------------------------------------------------------------
// Kernel 1: X = inputs @ W + b (4096 x 1536, K=768) with TF32 tensor cores.
// 128x128 block tile, BK=32, 256 threads (8 warps, 4x2), warp tile 32x64.
// cp.async double-buffered. Fused bias + RoPE + scatter epilogue.
// ---------------------------------------------------------------------------
#define AS_STRIDE 36     // 32 + 4   -> bank = 4g + tig (conflict-free)
#define BS_STRIDE 136    // 128 + 8  -> bank = 8*tig + g (conflict-free)
#define AS_FLOATS (128 * AS_STRIDE)       // 4608
#define BS_FLOATS (32 * BS_STRIDE)        // 4352
#define STAGE_FLOATS (AS_FLOATS + BS_FLOATS)  // 8960
#define G1_SMEM_BYTES (2 * STAGE_FLOATS * 4)  // 71680

__global__ void __launch_bounds__(256)
gemm1_rope_tc(const float* __restrict__ A,     // [4096][768]
              const float* __restrict__ W,     // [768][1536]
              const float* __restrict__ bias)  // [1536]
{
    extern __shared__ float sm[];

    const int t    = threadIdx.x;
    const int lane = t & 31;
    const int warp = t >> 5;
    const int g    = lane >> 2;     // 0..7
    const int tig  = lane & 3;      // 0..3
    const int wm   = warp >> 1;     // 0..3
    const int wn   = warp & 1;      // 0..1
    const int m0   = blockIdx.y * 128;
    const int n0   = blockIdx.x * 128;

    float acc[2][8][4];
    #pragma unroll
    for (int mt = 0; mt < 2; mt++)
        #pragma unroll
        for (int nt = 0; nt < 8; nt++)
            #pragma unroll
            for (int c = 0; c < 4; c++) acc[mt][nt][c] = 0.0f;

    auto load_tile = [&](int buf, int k0) {
        float* as = sm + buf * STAGE_FLOATS;
        float* bs = as + AS_FLOATS;
        #pragma unroll
        for (int i = 0; i < 4; i++) {
            int fid = t + 256 * i;
            int r = fid >> 3;            // 8 float4 per 32-wide row
            int c = (fid & 7) * 4;
            cp_async16(as + r * AS_STRIDE + c, A + (size_t)(m0 + r) * HID_ + k0 + c);
        }
        #pragma unroll
        for (int i = 0; i < 4; i++) {
            int fid = t + 256 * i;
            int r = fid >> 5;            // 32 float4 per 128-wide row
            int c = (fid & 31) * 4;
            cp_async16(bs + r * BS_STRIDE + c, W + (size_t)(k0 + r) * OD_ + n0 + c);
        }
        CP_COMMIT();
    };

    load_tile(0, 0);
    int buf = 0;

    for (int kt = 0; kt < HID_ / 32; kt++) {
        CP_WAIT0();
        __syncthreads();
        if (kt + 1 < HID_ / 32) load_tile(buf ^ 1, (kt + 1) * 32);

        const float* as = sm + buf * STAGE_FLOATS;
        const float* bs = as + AS_FLOATS;

        #pragma unroll
        for (int kk = 0; kk < 4; kk++) {
            const int k8 = kk * 8;
            uint32_t afrag[2][4];
            #pragma unroll
            for (int mt = 0; mt < 2; mt++) {
                const int mrow = wm * 32 + mt * 16;
                afrag[mt][0] = f2tf32(as[(mrow + g    ) * AS_STRIDE + k8 + tig    ]);
                afrag[mt][1] = f2tf32(as[(mrow + g + 8) * AS_STRIDE + k8 + tig    ]);
                afrag[mt][2] = f2tf32(as[(mrow + g    ) * AS_STRIDE + k8 + tig + 4]);
                afrag[mt][3] = f2tf32(as[(mrow + g + 8) * AS_STRIDE + k8 + tig + 4]);
            }
            #pragma unroll
            for (int nt = 0; nt < 8; nt++) {
                const int ncol = wn * 64 + nt * 8;
                uint32_t bfrag[2];
                bfrag[0] = f2tf32(bs[(k8 + tig    ) * BS_STRIDE + ncol + g]);
                bfrag[1] = f2tf32(bs[(k8 + tig + 4) * BS_STRIDE + ncol + g]);
                mma_tf32(acc[0][nt], afrag[0], bfrag);
                mma_tf32(acc[1][nt], afrag[1], bfrag);
            }
        }
        buf ^= 1;
    }

    // Epilogue: bias + RoPE + scatter to g_q / g_k ([b*h][l][d])
    // Thread owns: rows m0 + wm*32 + mt*16 + g (+8), cols n0 + wn*64 + nt*8 + 2*tig (+1)
    #pragma unroll
    for (int mt = 0; mt < 2; mt++) {
        #pragma unroll
        for (int half = 0; half < 2; half++) {
            const int m  = m0 + wm * 32 + mt * 16 + g + half * 8;
            const int l  = m & (LL_ - 1);
            const int b_ = m >> 9;
            #pragma unroll
            for (int nt = 0; nt < 8; nt++) {
                const int n = n0 + wn * 64 + nt * 8 + 2 * tig;   // even col
                float e = acc[mt][nt][half * 2 + 0] + bias[n];
                float o = acc[mt][nt][half * 2 + 1] + bias[n + 1];
                const int h  = n >> 7;
                const int qk = (n >> 6) & 1;
                const int d  = n & 63;
                const int p  = d >> 1;
                const float s = g_sin[l * 32 + p];
                const float c = g_cos[l * 32 + p];
                float2 v = make_float2(e * c - o * s, e * s + o * c);
                float* dst = (qk ? g_k : g_q)
                           + ((size_t)(b_ * HEADS_ + h) * LL_ + l) * HS_ + d;
                *(float2*)dst = v;
            }
        }
    }
}

// ---------------------------------------------------------------------------
// Kernel 2: logits[b,h,m,n] = (q . k) / 8, masked; TF32 tensor cores.
// 64x64 tile, 128 threads (4 warps, 2x2), warp tile 32x32, K=64 resident.
// Both Q and K tiles kept [seq][d] at stride 68 -> conflict-free frags.
// ---------------------------------------------------------------------------
#define QK_STRIDE 68     // 64 + 4 -> bank = 4g + tig (conflict-free)

__global__ void __launch_bounds__(128)
attn_logits_tc(const int* __restrict__ am,   // [8][512]
               float* __restrict__ out)      // [96][512][512]
{
    const int bh = blockIdx.z;
    const int tm = blockIdx.y;
    const int tn = blockIdx.x;
    const int t  = threadIdx.x;
    const int b_ = bh / HEADS_;
    const int m0 = tm * 64;
    const int n0 = tn * 64;
    float* obase = out + (size_t)bh * LL_ * LL_;

    if (tm > tn) {
        // fully below diagonal -> neg_inf fill, no loads/compute
        const float4 nv = make_float4(NEG_INF_F, NEG_INF_F, NEG_INF_F, NEG_INF_F);
        #pragma unroll
        for (int i = t; i < 1024; i += 128) {
            int r = i >> 4;
            int c = (i & 15) * 4;
            *(float4*)&obase[(size_t)(m0 + r) * LL_ + n0 + c] = nv;
        }
        return;
    }

    __shared__ float Qs[64 * QK_STRIDE];
    __shared__ float Ks[64 * QK_STRIDE];
    __shared__ int   rmv[64], cmv[64];

    const float* qb = g_q + ((size_t)bh * LL_ + m0) * HS_;
    const float* kb = g_k + ((size_t)bh * LL_ + n0) * HS_;

    #pragma unroll
    for (int i = 0; i < 8; i++) {
        int fid = t + 128 * i;
        int r = fid >> 4;
        int c = (fid & 15) * 4;
        cp_async16(&Qs[r * QK_STRIDE + c], qb + r * HS_ + c);
        cp_async16(&Ks[r * QK_STRIDE + c], kb + r * HS_ + c);
    }
    CP_COMMIT();
    if (t < 64)       rmv[t]      = am[b_ * LL_ + m0 + t];
    else if (t < 128) cmv[t - 64] = am[b_ * LL_ + n0 + (t - 64)];
    CP_WAIT0();
    __syncthreads();

    const int lane = t & 31;
    const int warp = t >> 5;
    const int g    = lane >> 2;
    const int tig  = lane & 3;
    const int wm   = warp >> 1;   // 0..1
    const int wn   = warp & 1;    // 0..1

    float acc[2][4][4];
    #pragma unroll
    for (int mt = 0; mt < 2; mt++)
        #pragma unroll
        for (int nt = 0; nt < 4; nt++)
            #pragma unroll
            for (int c = 0; c < 4; c++) acc[mt][nt][c] = 0.0f;

    #pragma unroll
    for (int kk = 0; kk < 8; kk++) {
        const int k8 = kk * 8;
        uint32_t afrag[2][4];
        #pragma unroll
        for (int mt = 0; mt < 2; mt++) {
            const int mrow = wm * 32 + mt * 16;
            afrag[mt][0] = f2tf32(Qs[(mrow + g    ) * QK_STRIDE + k8 + tig    ]);
            afrag[mt][1] = f2tf32(Qs[(mrow + g + 8) * QK_STRIDE + k8 + tig    ]);
            afrag[mt][2] = f2tf32(Qs[(mrow + g    ) * QK_STRIDE + k8 + tig + 4]);
            afrag[mt][3] = f2tf32(Qs[(mrow + g + 8) * QK_STRIDE + k8 + tig + 4]);
        }
        #pragma unroll
        for (int nt = 0; nt < 4; nt++) {
            const int nrow = wn * 32 + nt * 8;
            uint32_t bfrag[2];
            bfrag[0] = f2tf32(Ks[(nrow + g) * QK_STRIDE + k8 + tig    ]);
            bfrag[1] = f2tf32(Ks[(nrow + g) * QK_STRIDE + k8 + tig + 4]);
            mma_tf32(acc[0][nt], afrag[0], bfrag);
            mma_tf32(acc[1][nt], afrag[1], bfrag);
        }
    }

    // Epilogue: scale, mask, store
    #pragma unroll
    for (int mt = 0; mt < 2; mt++) {
        #pragma unroll
        for (int half = 0; half < 2; half++) {
            const int mi = wm * 32 + mt * 16 + g + half * 8;
            const int m  = m0 + mi;
            const bool rok = (rmv[mi] != 0);
            #pragma unroll
            for (int nt = 0; nt < 4; nt++) {
                const int ni = wn * 32 + nt * 8 + 2 * tig;
                const int n = n0 + ni;
                float x0 = acc[mt][nt][half * 2 + 0] * 0.125f;
                float x1 = acc[mt][nt][half * 2 + 1] * 0.125f;
                if (m > n     || !rok || cmv[ni]     == 0) x0 = NEG_INF_F;
                if (m > n + 1 || !rok || cmv[ni + 1] == 0) x1 = NEG_INF_F;
                *(float2*)&obase[(size_t)m * LL_ + n] = make_float2(x0, x1);
            }
        }
    }
}

// ---------------------------------------------------------------------------
// Entry point
// ---------------------------------------------------------------------------
extern "C" void kernel_launch(void* const* d_in, const int* in_sizes, int n_in,
                              void* d_out, int out_size) {
    const float* inputs = (const float*)d_in[0];  // [8,512,768]
    const float* W      = (const float*)d_in[1];  // [768,1536]
    const float* bias   = (const float*)d_in[2];  // [1536]
    const int*   amask  = (const int*)d_in[3];    // [8,512]
    float* out = (float*)d_out;                   // [8,12,512,512]

    cudaFuncSetAttribute(gemm1_rope_tc,
                         cudaFuncAttributeMaxDynamicSharedMemorySize, G1_SMEM_BYTES);

    rope_table_kernel<<<(LL_ * 32 + 255) / 256, 256>>>();
    gemm1_rope_tc<<<dim3(OD_ / 128, M1_ / 128), 256, G1_SMEM_BYTES>>>(inputs, W, bias);
    attn_logits_tc<<<dim3(LL_ / 64, LL_ / 64, BH_), 128>>>(amask, out);
}

// round 3
// speedup vs baseline: 4.9568x; 1.4379x over previous
#include <cuda_runtime.h>
#include <cuda_bf16.h>
#include <math.h>
#include <stdint.h>

// Problem constants
#define BB_    8
#define LL_    512
#define HEADS_ 12
#define HS_    64
#define HID_   768
#define OD_    1536          // HEADS*2*HS
#define M1_    (BB_*LL_)     // 4096
#define BH_    (BB_*HEADS_)  // 96
#define NEG_INF_F (-3.4028234663852886e38f)

// Scratch (device globals — no allocations allowed)
__device__ __nv_bfloat16 g_Abf[M1_ * HID_];   // inputs, bf16
__device__ __nv_bfloat16 g_Wbf[HID_ * OD_];   // W, bf16
__device__ __nv_bfloat16 g_q[BH_ * LL_ * HS_]; // [b*h][l][d]
__device__ __nv_bfloat16 g_k[BH_ * LL_ * HS_];
__device__ float g_sin[LL_ * 32];
__device__ float g_cos[LL_ * 32];

// ---------------------------------------------------------------------------
// PTX helpers
// ---------------------------------------------------------------------------
__device__ __forceinline__ void cp_async16(void* smem, const void* gmem) {
    uint32_t s = (uint32_t)__cvta_generic_to_shared(smem);
    asm volatile("cp.async.ca.shared.global [%0], [%1], 16;\n" :: "r"(s), "l"(gmem));
}
#define CP_COMMIT() asm volatile("cp.async.commit_group;\n")
#define CP_WAIT0()  asm volatile("cp.async.wait_group 0;\n")

__device__ __forceinline__ void ldsm_x4(uint32_t* r, const void* p) {
    uint32_t a = (uint32_t)__cvta_generic_to_shared(p);
    asm volatile("ldmatrix.sync.aligned.m8n8.x4.shared.b16 {%0,%1,%2,%3},[%4];"
                 : "=r"(r[0]), "=r"(r[1]), "=r"(r[2]), "=r"(r[3]) : "r"(a));
}
__device__ __forceinline__ void ldsm_x4_t(uint32_t* r, const void* p) {
    uint32_t a = (uint32_t)__cvta_generic_to_shared(p);
    asm volatile("ldmatrix.sync.aligned.m8n8.x4.trans.shared.b16 {%0,%1,%2,%3},[%4];"
                 : "=r"(r[0]), "=r"(r[1]), "=r"(r[2]), "=r"(r[3]) : "r"(a));
}

// D += A(m16k16) * B(k16n8), bf16 in, f32 accum
__device__ __forceinline__ void mma_bf16(float* d, const uint32_t* a, const uint32_t* b) {
    asm volatile(
        "mma.sync.aligned.m16n8k16.row.col.f32.bf16.bf16.f32 "
        "{%0,%1,%2,%3},{%4,%5,%6,%7},{%8,%9},{%0,%1,%2,%3};\n"
        : "+f"(d[0]), "+f"(d[1]), "+f"(d[2]), "+f"(d[3])
        : "r"(a[0]), "r"(a[1]), "r"(a[2]), "r"(a[3]), "r"(b[0]), "r"(b[1]));
}

// ---------------------------------------------------------------------------
// Kernel 0: convert A,W to bf16 + build RoPE tables (single launch)
// ---------------------------------------------------------------------------
#define NA4_ ((M1_ * HID_) / 4)   // 786432 float4 chunks of A
#define NW4_ ((HID_ * OD_) / 4)   // 294912 float4 chunks of W
#define NT_  (LL_ * 32)           // 16384 table entries

__global__ void prep_kernel(const float* __restrict__ A, const float* __restrict__ W) {
    int idx = blockIdx.x * blockDim.x + threadIdx.x;
    if (idx < NA4_) {
        float4 v = ((const float4*)A)[idx];
        __nv_bfloat162 lo = __floats2bfloat162_rn(v.x, v.y);
        __nv_bfloat162 hi = __floats2bfloat162_rn(v.z, v.w);
        ((uint2*)g_Abf)[idx] = make_uint2(*(uint32_t*)&lo, *(uint32_t*)&hi);
    } else if (idx < NA4_ + NW4_) {
        int j = idx - NA4_;
        float4 v = ((const float4*)W)[j];
        __nv_bfloat162 lo = __floats2bfloat162_rn(v.x, v.y);
        __nv_bfloat162 hi = __floats2bfloat162_rn(v.z, v.w);
        ((uint2*)g_Wbf)[j] = make_uint2(*(uint32_t*)&lo, *(uint32_t*)&hi);
    } else if (idx < NA4_ + NW4_ + NT_) {
        int j = idx - NA4_ - NW4_;
        int l = j >> 5;
        int p = j & 31;
        float inv = powf(10000.0f, -(float)p / 32.0f);
        float ang = (float)l * inv;
        g_sin[j] = sinf(ang);
        g_cos[j] = cosf(ang);
    }
}

// ---------------------------------------------------------------------------
// Kernel 1: X = A @ W + b (4096 x 1536, K=768), bf16 tensor cores + ldmatrix.
// 128x128 block, BK=32, 8 warps (4x2), warp tile 32x64.
// Fused bias + RoPE + scatter (bf16) epilogue.
// ---------------------------------------------------------------------------
#define G1_AS_STRIDE 40    // bf16 (80B rows -> conflict-free LDSM)
#define G1_BS_STRIDE 136   // bf16 (272B rows -> conflict-free LDSM.T)
#define G1_AS (128 * G1_AS_STRIDE)   // 5120 bf16
#define G1_BS (32 * G1_BS_STRIDE)    // 4352 bf16
#define G1_STAGE (G1_AS + G1_BS)     // 9472 bf16 -> 18944 B/stage

__global__ void __launch_bounds__(256)
gemm1_rope_bf16(const float* __restrict__ bias)
{
    __shared__ __nv_bfloat16 sm[2 * G1_STAGE];   // 37.9 KB

    const int t    = threadIdx.x;
    const int lane = t & 31;
    const int warp = t >> 5;
    const int g    = lane >> 2;
    const int tig  = lane & 3;
    const int wm   = warp >> 1;     // 0..3
    const int wn   = warp & 1;      // 0..1
    const int m0   = blockIdx.y * 128;
    const int n0   = blockIdx.x * 128;

    float acc[2][8][4];
    #pragma unroll
    for (int mt = 0; mt < 2; mt++)
        #pragma unroll
        for (int j = 0; j < 8; j++)
            #pragma unroll
            for (int c = 0; c < 4; c++) acc[mt][j][c] = 0.0f;

    auto load_tile = [&](int buf, int k0) {
        __nv_bfloat16* as = sm + buf * G1_STAGE;
        __nv_bfloat16* bs = as + G1_AS;
        #pragma unroll
        for (int i = 0; i < 2; i++) {          // A: 512 x 16B chunks
            int ch = t + 256 * i;
            int r = ch >> 2;
            int c = (ch & 3) * 8;
            cp_async16(as + r * G1_AS_STRIDE + c,
                       g_Abf + (size_t)(m0 + r) * HID_ + k0 + c);
        }
        #pragma unroll
        for (int i = 0; i < 2; i++) {          // B: 512 x 16B chunks
            int ch = t + 256 * i;
            int r = ch >> 4;
            int c = (ch & 15) * 8;
            cp_async16(bs + r * G1_BS_STRIDE + c,
                       g_Wbf + (size_t)(k0 + r) * OD_ + n0 + c);
        }
        CP_COMMIT();
    };

    load_tile(0, 0);
    int buf = 0;

    const int a_row = (lane & 15);
    const int a_coff = (lane >> 4) * 8;

    for (int kt = 0; kt < HID_ / 32; kt++) {
        CP_WAIT0();
        __syncthreads();
        if (kt + 1 < HID_ / 32) load_tile(buf ^ 1, (kt + 1) * 32);

        const __nv_bfloat16* as = sm + buf * G1_STAGE;
        const __nv_bfloat16* bs = as + G1_AS;

        #pragma unroll
        for (int kk = 0; kk < 2; kk++) {
            const int k16 = kk * 16;
            uint32_t af[2][4];
            #pragma unroll
            for (int mt = 0; mt < 2; mt++) {
                int row = wm * 32 + mt * 16 + a_row;
                ldsm_x4(af[mt], as + row * G1_AS_STRIDE + k16 + a_coff);
            }
            #pragma unroll
            for (int nt = 0; nt < 4; nt++) {
                uint32_t bfm[4];
                int krow = k16 + a_row;
                int ncol = wn * 64 + nt * 16 + a_coff;
                ldsm_x4_t(bfm, bs + krow * G1_BS_STRIDE + ncol);
                mma_bf16(acc[0][2 * nt],     af[0], &bfm[0]);
                mma_bf16(acc[0][2 * nt + 1], af[0], &bfm[2]);
                mma_bf16(acc[1][2 * nt],     af[1], &bfm[0]);
                mma_bf16(acc[1][2 * nt + 1], af[1], &bfm[2]);
            }
        }
        buf ^= 1;
    }

    // Epilogue: bias + RoPE + scatter bf16 to g_q/g_k ([b*h][l][d])
    #pragma unroll
    for (int mt = 0; mt < 2; mt++) {
        #pragma unroll
        for (int half = 0; half < 2; half++) {
            const int m  = m0 + wm * 32 + mt * 16 + g + half * 8;
            const int l  = m & (LL_ - 1);
            const int b_ = m >> 9;
            #pragma unroll
            for (int j = 0; j < 8; j++) {
                const int n = n0 + wn * 64 + j * 8 + 2 * tig;     // even col
                float e = acc[mt][j][half * 2 + 0] + bias[n];
                float o = acc[mt][j][half * 2 + 1] + bias[n + 1];
                const int h  = n >> 7;
                const int qk = (n >> 6) & 1;
                const int d  = n & 63;
                const int p  = d >> 1;
                const float s = g_sin[l * 32 + p];
                const float c = g_cos[l * 32 + p];
                __nv_bfloat162 v = __floats2bfloat162_rn(e * c - o * s, e * s + o * c);
                __nv_bfloat16* dst = (qk ? g_k : g_q)
                    + ((size_t)(b_ * HEADS_ + h) * LL_ + l) * HS_ + d;
                *(__nv_bfloat162*)dst = v;
            }
        }
    }
}

// ---------------------------------------------------------------------------
// Kernel 2: logits = (q.k)/8, masked; bf16 tensor cores.
// 64x64 tile, 4 warps (2x2), warp tile 32x32, K=64 resident (4 k16 steps).
// K fragments via NON-trans ldmatrix (Ks[n][d] is already B-fragment order).
// ---------------------------------------------------------------------------
#define QK_STRIDE 72   // bf16 (144B rows -> conflict-free LDSM)

__global__ void __launch_bounds__(128)
attn_logits_bf16(const int* __restrict__ am,   // [8][512]
                 float* __restrict__ out)      // [96][512][512]
{
    const int bh = blockIdx.z;
    const int tm = blockIdx.y;
    const int tn = blockIdx.x;
    const int t  = threadIdx.x;
    const int b_ = bh / HEADS_;
    const int m0 = tm * 64;
    const int n0 = tn * 64;
    float* obase = out + (size_t)bh * LL_ * LL_;

    if (tm > tn) {
        const float4 nv = make_float4(NEG_INF_F, NEG_INF_F, NEG_INF_F, NEG_INF_F);
        #pragma unroll
        for (int i = t; i < 1024; i += 128) {
            int r = i >> 4;
            int c = (i & 15) * 4;
            *(float4*)&obase[(size_t)(m0 + r) * LL_ + n0 + c] = nv;
        }
        return;
    }

    __shared__ __nv_bfloat16 Qs[64 * QK_STRIDE];
    __shared__ __nv_bfloat16 Ks[64 * QK_STRIDE];
    __shared__ int rmv[64], cmv[64];

    const __nv_bfloat16* qb = g_q + ((size_t)bh * LL_ + m0) * HS_;
    const __nv_bfloat16* kb = g_k + ((size_t)bh * LL_ + n0) * HS_;

    #pragma unroll
    for (int i = 0; i < 4; i++) {              // 512 x 16B chunks each
        int ch = t + 128 * i;
        int r = ch >> 3;
        int c = (ch & 7) * 8;
        cp_async16(&Qs[r * QK_STRIDE + c], qb + r * HS_ + c);
        cp_async16(&Ks[r * QK_STRIDE + c], kb + r * HS_ + c);
    }
    CP_COMMIT();
    if (t < 64)       rmv[t]      = am[b_ * LL_ + m0 + t];
    else if (t < 128) cmv[t - 64] = am[b_ * LL_ + n0 + (t - 64)];
    CP_WAIT0();
    __syncthreads();

    const int lane = t & 31;
    const int warp = t >> 5;
    const int g    = lane >> 2;
    const int tig  = lane & 3;
    const int wm   = warp >> 1;   // 0..1
    const int wn   = warp & 1;    // 0..1

    float acc[2][4][4];
    #pragma unroll
    for (int mt = 0; mt < 2; mt++)
        #pragma unroll
        for (int j = 0; j < 4; j++)
            #pragma unroll
            for (int c = 0; c < 4; c++) acc[mt][j][c] = 0.0f;

    const int a_row  = (lane & 15);
    const int a_coff = (lane >> 4) * 8;
    const int b_row  = (lane & 7) + 8 * (lane >> 4);     // n within 16-tile
    const int b_coff = 8 * ((lane >> 3) & 1);            // k half

    #pragma unroll
    for (int kk = 0; kk < 4; kk++) {
        const int k16 = kk * 16;
        uint32_t qf[2][4];
        #pragma unroll
        for (int mt = 0; mt < 2; mt++) {
            int row = wm * 32 + mt * 16 + a_row;
            ldsm_x4(qf[mt], &Qs[row * QK_STRIDE + k16 + a_coff]);
        }
        #pragma unroll
        for (int nt = 0; nt < 2; nt++) {
            uint32_t kf[4];
            int nrow = wn * 32 + nt * 16 + b_row;
            ldsm_x4(kf, &Ks[nrow * QK_STRIDE + k16 + b_coff]);
            mma_bf16(acc[0][2 * nt],     qf[0], &kf[0]);
            mma_bf16(acc[0][2 * nt + 1], qf[0], &kf[2]);
            mma_bf16(acc[1][2 * nt],     qf[1], &kf[0]);
            mma_bf16(acc[1][2 * nt + 1], qf[1], &kf[2]);
        }
    }

    // Epilogue: scale, mask, store
    #pragma unroll
    for (int mt = 0; mt < 2; mt++) {
        #pragma unroll
        for (int half = 0; half < 2; half++) {
            const int mi = wm * 32 + mt * 16 + g + half * 8;
            const int m  = m0 + mi;
            const bool rok = (rmv[mi] != 0);
            #pragma unroll
            for (int j = 0; j < 4; j++) {
                const int ni = wn * 32 + j * 8 + 2 * tig;
                const int n  = n0 + ni;
                float x0 = acc[mt][j][half * 2 + 0] * 0.125f;
                float x1 = acc[mt][j][half * 2 + 1] * 0.125f;
                if (m > n     || !rok || cmv[ni]     == 0) x0 = NEG_INF_F;
                if (m > n + 1 || !rok || cmv[ni + 1] == 0) x1 = NEG_INF_F;
                *(float2*)&obase[(size_t)m * LL_ + n] = make_float2(x0, x1);
            }
        }
    }
}

// ---------------------------------------------------------------------------
// Entry point
// ---------------------------------------------------------------------------
extern "C" void kernel_launch(void* const* d_in, const int* in_sizes, int n_in,
                              void* d_out, int out_size) {
    const float* inputs = (const float*)d_in[0];  // [8,512,768]
    const float* W      = (const float*)d_in[1];  // [768,1536]
    const float* bias   = (const float*)d_in[2];  // [1536]
    const int*   amask  = (const int*)d_in[3];    // [8,512]
    float* out = (float*)d_out;                   // [8,12,512,512]

    const int prep_total = NA4_ + NW4_ + NT_;
    prep_kernel<<<(prep_total + 255) / 256, 256>>>(inputs, W);
    gemm1_rope_bf16<<<dim3(OD_ / 128, M1_ / 128), 256>>>(bias);
    attn_logits_bf16<<<dim3(LL_ / 64, LL_ / 64, BH_), 128>>>(amask, out);
}

// round 5
// speedup vs baseline: 5.7151x; 1.1530x over previous
#include <cuda_runtime.h>
#include <math.h>
#include <stdint.h>

// Problem constants
#define BB_    8
#define LL_    512
#define HEADS_ 12
#define HS_    64
#define HID_   768
#define OD_    1536          // HEADS*2*HS
#define M1_    (BB_*LL_)     // 4096
#define BH_    (BB_*HEADS_)  // 96
#define NEG_INF_F (-3.4028234663852886e38f)

// Scratch (device globals — no allocations allowed)
__device__ uint8_t g_Af8[M1_ * HID_];     // inputs e4m3 [4096][768]
__device__ uint8_t g_WTf8[OD_ * HID_];    // W^T e4m3 [1536][768]
__device__ uint8_t g_q8[BH_ * LL_ * HS_]; // [b*h][l][d] e4m3
__device__ uint8_t g_k8[BH_ * LL_ * HS_];
__device__ float g_sin[LL_ * 32];
__device__ float g_cos[LL_ * 32];

// ---------------------------------------------------------------------------
// PTX helpers (portable ISA only — compute_103 target has no 'a' features)
// ---------------------------------------------------------------------------
__device__ __forceinline__ uint32_t smem_u32(const void* p) {
    return (uint32_t)__cvta_generic_to_shared(p);
}
__device__ __forceinline__ void cp16(uint32_t s, const void* g) {
    asm volatile("cp.async.cg.shared.global [%0], [%1], 16;\n" :: "r"(s), "l"(g));
}
#define CP_COMMIT() asm volatile("cp.async.commit_group;\n")
#define CP_WAIT0()  asm volatile("cp.async.wait_group 0;\n")
#define CP_WAIT2()  asm volatile("cp.async.wait_group 2;\n")

// cvt packs first source into the HIGH byte: d = {hi, lo}
__device__ __forceinline__ uint16_t f2e4m3x2(float hi, float lo) {
    uint16_t r;
    asm("cvt.rn.satfinite.e4m3x2.f32 %0, %1, %2;\n" : "=h"(r) : "f"(hi), "f"(lo));
    return r;
}

__device__ __forceinline__ void ldsm_x4(uint32_t* r, const void* p) {
    uint32_t a = smem_u32(p);
    asm volatile("ldmatrix.sync.aligned.m8n8.x4.shared.b16 {%0,%1,%2,%3},[%4];"
                 : "=r"(r[0]), "=r"(r[1]), "=r"(r[2]), "=r"(r[3]) : "r"(a));
}

// D += A(m16k32) * B(k32n8), e4m3 in, f32 accum
__device__ __forceinline__ void mma_fp8(float* d, const uint32_t* a, const uint32_t* b) {
    asm volatile(
        "mma.sync.aligned.m16n8k32.row.col.f32.e4m3.e4m3.f32 "
        "{%0,%1,%2,%3},{%4,%5,%6,%7},{%8,%9},{%0,%1,%2,%3};\n"
        : "+f"(d[0]), "+f"(d[1]), "+f"(d[2]), "+f"(d[3])
        : "r"(a[0]), "r"(a[1]), "r"(a[2]), "r"(a[3]), "r"(b[0]), "r"(b[1]));
}

// ---------------------------------------------------------------------------
// Kernel 0a: convert A to e4m3 + RoPE tables
// ---------------------------------------------------------------------------
#define NA4_ ((M1_ * HID_) / 4)   // 786432
#define NT_  (LL_ * 32)           // 16384

__global__ void prep_kernel(const float* __restrict__ A) {
    int idx = blockIdx.x * blockDim.x + threadIdx.x;
    if (idx < NA4_) {
        float4 v = ((const float4*)A)[idx];
        uint32_t lo = f2e4m3x2(v.y, v.x);
        uint32_t hi = f2e4m3x2(v.w, v.z);
        ((uint32_t*)g_Af8)[idx] = lo | (hi << 16);
    } else if (idx < NA4_ + NT_) {
        int j = idx - NA4_;
        int l = j >> 5;
        int p = j & 31;
        float inv = powf(10000.0f, -(float)p / 32.0f);
        float ang = (float)l * inv;
        g_sin[j] = sinf(ang);
        g_cos[j] = cosf(ang);
    }
}

// ---------------------------------------------------------------------------
// Kernel 0b: W [768][1536] fp32 -> g_WTf8 [1536][768] e4m3 (tiled transpose)
// ---------------------------------------------------------------------------
__global__ void __launch_bounds__(256)
transposeW_kernel(const float* __restrict__ W) {
    __shared__ float tile[32][33];
    const int bx = blockIdx.x;      // OD/32 = 48
    const int by = blockIdx.y;      // HID/32 = 24
    const int c  = threadIdx.x & 31;
    const int r4 = threadIdx.x >> 5;
    #pragma unroll
    for (int i = 0; i < 4; i++) {
        int r = r4 * 4 + i;
        tile[r][c] = W[(size_t)(by * 32 + r) * OD_ + bx * 32 + c];
    }
    __syncthreads();
    #pragma unroll
    for (int i = 0; i < 4; i++) {
        int r = r4 * 4 + i;
        g_WTf8[(size_t)(bx * 32 + r) * HID_ + by * 32 + c] =
            (uint8_t)(f2e4m3x2(0.0f, tile[c][r]) & 0xFF);
    }
}

// ---------------------------------------------------------------------------
// Kernel 1: X = A @ W + b (4096x1536, K=768), fp8 mma.sync m16n8k32.
// 128x128 block, BK=64, 8 warps (4x2), warp tile 32x64.
// 4-stage cp.async ring. Fused bias + RoPE + e4m3 scatter epilogue.
// ---------------------------------------------------------------------------
#define A8_STRIDE   80                     // bytes per 64-fp8 row (pad 16)
#define TILE8_BYTES (128 * A8_STRIDE)      // 10240
#define STAGE8      (2 * TILE8_BYTES)      // 20480 (A + B)
#define G1_DSMEM    (4 * STAGE8)           // 81920

__global__ void __launch_bounds__(256, 2)
gemm1_fp8(const float* __restrict__ bias) {
    extern __shared__ uint8_t sm8[];

    const int t    = threadIdx.x;
    const int lane = t & 31;
    const int warp = t >> 5;
    const int g    = lane >> 2;
    const int tig  = lane & 3;
    const int wm   = warp >> 1;     // 0..3
    const int wn   = warp & 1;      // 0..1
    const int m0   = blockIdx.y * 128;
    const int n0   = blockIdx.x * 128;

    float acc[2][8][4];
    #pragma unroll
    for (int mt = 0; mt < 2; mt++)
        #pragma unroll
        for (int j = 0; j < 8; j++)
            #pragma unroll
            for (int c = 0; c < 4; c++) acc[mt][j][c] = 0.0f;

    auto load_tile = [&](int buf, int k0) {
        uint8_t* as = sm8 + buf * STAGE8;
        uint8_t* bs = as + TILE8_BYTES;
        #pragma unroll
        for (int i = 0; i < 2; i++) {          // A: 512 x 16B chunks
            int ch = t + 256 * i;
            int r = ch >> 2;
            int cc = (ch & 3) * 16;
            cp16(smem_u32(as + r * A8_STRIDE + cc),
                 g_Af8 + (size_t)(m0 + r) * HID_ + k0 + cc);
        }
        #pragma unroll
        for (int i = 0; i < 2; i++) {          // B: 512 x 16B chunks
            int ch = t + 256 * i;
            int r = ch >> 2;
            int cc = (ch & 3) * 16;
            cp16(smem_u32(bs + r * A8_STRIDE + cc),
                 g_WTf8 + (size_t)(n0 + r) * HID_ + k0 + cc);
        }
        CP_COMMIT();
    };

    load_tile(0, 0);
    load_tile(1, 64);
    load_tile(2, 128);

    const int a_row  = lane & 15;
    const int a_coff = (lane >> 4) * 16;                    // byte col
    const int b_row  = (lane & 7) + 8 * (lane >> 4);
    const int b_coff = 16 * ((lane >> 3) & 1);              // byte col

    for (int kt = 0; kt < 12; kt++) {
        const int buf = kt & 3;
        CP_WAIT2();
        __syncthreads();
        if (kt + 3 < 12) load_tile((kt + 3) & 3, (kt + 3) * 64);
        else             CP_COMMIT();   // keep group count uniform for WAIT2

        const uint8_t* as = sm8 + buf * STAGE8;
        const uint8_t* bs = as + TILE8_BYTES;

        #pragma unroll
        for (int kk = 0; kk < 2; kk++) {
            const int k32 = kk * 32;
            uint32_t af[2][4];
            #pragma unroll
            for (int mt = 0; mt < 2; mt++) {
                int row = wm * 32 + mt * 16 + a_row;
                ldsm_x4(af[mt], as + row * A8_STRIDE + k32 + a_coff);
            }
            #pragma unroll
            for (int nt = 0; nt < 4; nt++) {
                uint32_t bf[4];
                int row = wn * 64 + nt * 16 + b_row;
                ldsm_x4(bf, bs + row * A8_STRIDE + k32 + b_coff);
                mma_fp8(acc[0][2 * nt],     af[0], &bf[0]);
                mma_fp8(acc[0][2 * nt + 1], af[0], &bf[2]);
                mma_fp8(acc[1][2 * nt],     af[1], &bf[0]);
                mma_fp8(acc[1][2 * nt + 1], af[1], &bf[2]);
            }
        }
    }

    // Epilogue: bias + RoPE + e4m3 scatter to g_q8/g_k8 ([b*h][l][d])
    #pragma unroll
    for (int mt = 0; mt < 2; mt++) {
        #pragma unroll
        for (int half = 0; half < 2; half++) {
            const int m  = m0 + wm * 32 + mt * 16 + g + half * 8;
            const int l  = m & (LL_ - 1);
            const int b_ = m >> 9;
            #pragma unroll
            for (int j = 0; j < 8; j++) {
                const int n = n0 + wn * 64 + j * 8 + 2 * tig;   // even col
                float e = acc[mt][j][half * 2 + 0] + bias[n];
                float o = acc[mt][j][half * 2 + 1] + bias[n + 1];
                const int h  = n >> 7;
                const int qk = (n >> 6) & 1;
                const int d  = n & 63;
                const int p  = d >> 1;
                const float s  = g_sin[l * 32 + p];
                const float co = g_cos[l * 32 + p];
                uint16_t v = f2e4m3x2(e * s + o * co, e * co - o * s);
                uint8_t* dst = (qk ? g_k8 : g_q8)
                    + ((size_t)(b_ * HEADS_ + h) * LL_ + l) * HS_ + d;
                *(uint16_t*)dst = v;
            }
        }
    }
}

// ---------------------------------------------------------------------------
// Kernel 2: logits = (q.k)/8, masked; fp8 mma.sync.
// 64x64 tile, 4 warps (2x2), warp tile 32x32, K=64 (2 k32 steps).
// ---------------------------------------------------------------------------
#define QK8_STRIDE 80

__global__ void __launch_bounds__(128)
attn_logits_fp8(const int* __restrict__ am, float* __restrict__ out) {
    const int bh = blockIdx.z;
    const int tm = blockIdx.y;
    const int tn = blockIdx.x;
    const int t  = threadIdx.x;
    const int b_ = bh / HEADS_;
    const int m0 = tm * 64;
    const int n0 = tn * 64;
    float* obase = out + (size_t)bh * LL_ * LL_;

    if (tm > tn) {
        const float4 nv = make_float4(NEG_INF_F, NEG_INF_F, NEG_INF_F, NEG_INF_F);
        #pragma unroll
        for (int i = t; i < 1024; i += 128) {
            int r = i >> 4;
            int c = (i & 15) * 4;
            *(float4*)&obase[(size_t)(m0 + r) * LL_ + n0 + c] = nv;
        }
        return;
    }

    __shared__ uint8_t Qs[64 * QK8_STRIDE];
    __shared__ uint8_t Ks[64 * QK8_STRIDE];
    __shared__ int rmv[64], cmv[64];

    const uint8_t* qb = g_q8 + ((size_t)bh * LL_ + m0) * HS_;
    const uint8_t* kb = g_k8 + ((size_t)bh * LL_ + n0) * HS_;

    #pragma unroll
    for (int i = 0; i < 2; i++) {              // 256 x 16B chunks each
        int ch = t + 128 * i;
        int r = ch >> 2;
        int c = (ch & 3) * 16;
        cp16(smem_u32(&Qs[r * QK8_STRIDE + c]), qb + r * HS_ + c);
        cp16(smem_u32(&Ks[r * QK8_STRIDE + c]), kb + r * HS_ + c);
    }
    CP_COMMIT();
    if (t < 64)       rmv[t]      = am[b_ * LL_ + m0 + t];
    else if (t < 128) cmv[t - 64] = am[b_ * LL_ + n0 + (t - 64)];
    CP_WAIT0();
    __syncthreads();

    const int lane = t & 31;
    const int warp = t >> 5;
    const int g    = lane >> 2;
    const int tig  = lane & 3;
    const int wm   = warp >> 1;   // 0..1
    const int wn   = warp & 1;    // 0..1

    float acc[2][4][4];
    #pragma unroll
    for (int mt = 0; mt < 2; mt++)
        #pragma unroll
        for (int j = 0; j < 4; j++)
            #pragma unroll
            for (int c = 0; c < 4; c++) acc[mt][j][c] = 0.0f;

    const int a_row  = lane & 15;
    const int a_coff = (lane >> 4) * 16;
    const int b_row  = (lane & 7) + 8 * (lane >> 4);
    const int b_coff = 16 * ((lane >> 3) & 1);

    #pragma unroll
    for (int kk = 0; kk < 2; kk++) {
        const int k32 = kk * 32;
        uint32_t qf[2][4];
        #pragma unroll
        for (int mt = 0; mt < 2; mt++) {
            int row = wm * 32 + mt * 16 + a_row;
            ldsm_x4(qf[mt], &Qs[row * QK8_STRIDE + k32 + a_coff]);
        }
        #pragma unroll
        for (int nt = 0; nt < 2; nt++) {
            uint32_t kf[4];
            int row = wn * 32 + nt * 16 + b_row;
            ldsm_x4(kf, &Ks[row * QK8_STRIDE + k32 + b_coff]);
            mma_fp8(acc[0][2 * nt],     qf[0], &kf[0]);
            mma_fp8(acc[0][2 * nt + 1], qf[0], &kf[2]);
            mma_fp8(acc[1][2 * nt],     qf[1], &kf[0]);
            mma_fp8(acc[1][2 * nt + 1], qf[1], &kf[2]);
        }
    }

    #pragma unroll
    for (int mt = 0; mt < 2; mt++) {
        #pragma unroll
        for (int half = 0; half < 2; half++) {
            const int mi = wm * 32 + mt * 16 + g + half * 8;
            const int m  = m0 + mi;
            const bool rok = (rmv[mi] != 0);
            #pragma unroll
            for (int j = 0; j < 4; j++) {
                const int ni = wn * 32 + j * 8 + 2 * tig;
                const int n  = n0 + ni;
                float x0 = acc[mt][j][half * 2 + 0] * 0.125f;
                float x1 = acc[mt][j][half * 2 + 1] * 0.125f;
                if (m > n     || !rok || cmv[ni]     == 0) x0 = NEG_INF_F;
                if (m > n + 1 || !rok || cmv[ni + 1] == 0) x1 = NEG_INF_F;
                *(float2*)&obase[(size_t)m * LL_ + n] = make_float2(x0, x1);
            }
        }
    }
}

// ---------------------------------------------------------------------------
// Entry point
// ---------------------------------------------------------------------------
extern "C" void kernel_launch(void* const* d_in, const int* in_sizes, int n_in,
                              void* d_out, int out_size) {
    const float* inputs = (const float*)d_in[0];  // [8,512,768]
    const float* W      = (const float*)d_in[1];  // [768,1536]
    const float* bias   = (const float*)d_in[2];  // [1536]
    const int*   amask  = (const int*)d_in[3];    // [8,512]
    float* out = (float*)d_out;                   // [8,12,512,512]

    cudaFuncSetAttribute(gemm1_fp8,
                         cudaFuncAttributeMaxDynamicSharedMemorySize, G1_DSMEM);

    prep_kernel<<<(NA4_ + NT_ + 255) / 256, 256>>>(inputs);
    transposeW_kernel<<<dim3(OD_ / 32, HID_ / 32), 256>>>(W);
    gemm1_fp8<<<dim3(OD_ / 128, M1_ / 128), 256, G1_DSMEM>>>(bias);
    attn_logits_fp8<<<dim3(LL_ / 64, LL_ / 64, BH_), 128>>>(amask, out);
}